// round 5
// baseline (speedup 1.0000x reference)
#include <cuda_runtime.h>

#define NS 512
#define NC 128
#define DIM 640
#define HOR 256
#define NB 148
#define NT 256

// ---------------- device scratch ----------------
static __device__ float g_V[NS*NS];
static __device__ float g_v[NS];
static __device__ float g_W[NS*DIM];      // W = V * F
static __device__ float g_Q[DIM*DIM];
static __device__ float g_q[DIM];
static __device__ float g_zv[NS];         // V f + v
static __device__ float g_Lsym[NC*NC];
static __device__ float g_invd[NC];
static __device__ float g_K[NC*NS];
static __device__ float g_k[NC];
static __device__ float g_fVf, g_fv;
static __device__ float g_delta[HOR];
static __device__ unsigned g_count = 0;
static __device__ unsigned g_sense = 0;

// smem float offsets
#define SM_A0 0
#define SM_B0 1088          // A buf: 16*68
#define SM_A1 2112
#define SM_B1 3200
#define SM_SCR 4224         // 64*68 transpose scratch
// chol/trsm reuse sh[0 .. 128*129)

__device__ __forceinline__ void gbar(unsigned ph) {
    __syncthreads();
    if (threadIdx.x == 0) {
        __threadfence();
        if (atomicAdd(&g_count, 1u) == NB - 1u) {
            g_count = 0u;
            __threadfence();
            atomicExch(&g_sense, ph);
        } else {
            while (*(volatile unsigned*)&g_sense != ph) { }
            __threadfence();
        }
    }
    __syncthreads();
}

#define MM16(av,bv) \
    acc[0][0] += av.x*bv.x; acc[0][1] += av.x*bv.y; acc[0][2] += av.x*bv.z; acc[0][3] += av.x*bv.w; \
    acc[1][0] += av.y*bv.x; acc[1][1] += av.y*bv.y; acc[1][2] += av.y*bv.z; acc[1][3] += av.y*bv.w; \
    acc[2][0] += av.z*bv.x; acc[2][1] += av.z*bv.y; acc[2][2] += av.z*bv.z; acc[2][3] += av.z*bv.w; \
    acc[3][0] += av.w*bv.x; acc[3][1] += av.w*bv.y; acc[3][2] += av.w*bv.z; acc[3][3] += av.w*bv.w;

__device__ __forceinline__ void compute16(const float* As, const float* Bs,
                                          float acc[4][4], int tx, int ty) {
    #pragma unroll
    for (int k2 = 0; k2 < 16; k2++) {
        float4 av = *(const float4*)&As[k2*68 + ty*4];
        float4 bv = *(const float4*)&Bs[k2*64 + tx*4];
        MM16(av, bv)
    }
}

// mirror a 64x64 tile of final values (held in acc) to the transposed location(s)
__device__ __forceinline__ void mirror_tile(float* scr, const float acc[4][4],
                                            int tx, int ty, int t,
                                            float* dst0, int ld0, float* dst1, int ld1,
                                            int r0, int c0) {
    #pragma unroll
    for (int i = 0; i < 4; i++) {
        float4 w; w.x = acc[i][0]; w.y = acc[i][1]; w.z = acc[i][2]; w.w = acc[i][3];
        *(float4*)&scr[(ty*4+i)*68 + tx*4] = w;
    }
    __syncthreads();
    int j = t >> 2, i4 = (t & 3)*16;
    #pragma unroll
    for (int m = 0; m < 4; m++) {
        float4 w;
        w.x = scr[(i4+4*m+0)*68 + j];
        w.y = scr[(i4+4*m+1)*68 + j];
        w.z = scr[(i4+4*m+2)*68 + j];
        w.w = scr[(i4+4*m+3)*68 + j];
        *(float4*)&dst0[(size_t)(c0+j)*ld0 + r0 + i4 + 4*m] = w;
        if (dst1) *(float4*)&dst1[(size_t)(c0+j)*ld1 + r0 + i4 + 4*m] = w;
    }
    __syncthreads();
}

__global__ __launch_bounds__(NT, 1)
void lqr_persistent(const float* __restrict__ F, const float* __restrict__ f,
                    const float* __restrict__ C, const float* __restrict__ c,
                    float* __restrict__ out) {
    extern __shared__ float sh[];
    const int b = blockIdx.x;
    const int t = threadIdx.x;
    const int tx = t & 15, ty = t >> 4;

    float* Ks_all = out;
    float* ks_all = out + (size_t)HOR*NC*NS;
    float* Vs_all = ks_all + (size_t)HOR*NC;
    float* vs_all = Vs_all + (size_t)HOR*NS*NS;
    float* co_all = vs_all + (size_t)HOR*NS;

    unsigned phase = *(volatile unsigned*)&g_sense;

    // ---- init ----
    for (int idx = b*NT + t; idx < NS*NS; idx += NB*NT)
        g_V[idx] = C[(idx >> 9)*DIM + (idx & 511)];
    for (int idx = b*NT + t; idx < NS; idx += NB*NT)
        g_v[idx] = c[idx];
    gbar(++phase);

    // loader index precompute
    const int l_row = t >> 2, l_k4 = (t & 3) << 2;       // transpose-A loader
    const int l_kk  = t >> 4, l_c4 = (t & 15) << 2;      // direct loader

    for (int step = 0; step < HOR; step++) {
        const int slot = HOR - 1 - step;

        // ============ P1: W = V*F (8x10 tiles) ; zv ============
        if (b < 80) {
            int r0 = (b/10)*64, c0 = (b%10)*64;
            float* Ac = sh + SM_A0; float* Bc = sh + SM_B0;
            float* An = sh + SM_A1; float* Bn = sh + SM_B1;
            float4 va = *(const float4*)&g_V[(r0+l_row)*NS + l_k4];
            float4 vb = *(const float4*)&F[l_kk*DIM + c0 + l_c4];
            Ac[(l_k4+0)*68+l_row]=va.x; Ac[(l_k4+1)*68+l_row]=va.y;
            Ac[(l_k4+2)*68+l_row]=va.z; Ac[(l_k4+3)*68+l_row]=va.w;
            *(float4*)&Bc[l_kk*64+l_c4] = vb;
            __syncthreads();
            float acc[4][4] = {};
            for (int k0 = 16; k0 < NS; k0 += 16) {
                va = *(const float4*)&g_V[(r0+l_row)*NS + k0 + l_k4];
                vb = *(const float4*)&F[(k0+l_kk)*DIM + c0 + l_c4];
                compute16(Ac, Bc, acc, tx, ty);
                An[(l_k4+0)*68+l_row]=va.x; An[(l_k4+1)*68+l_row]=va.y;
                An[(l_k4+2)*68+l_row]=va.z; An[(l_k4+3)*68+l_row]=va.w;
                *(float4*)&Bn[l_kk*64+l_c4] = vb;
                __syncthreads();
                float* tp;
                tp = Ac; Ac = An; An = tp;
                tp = Bc; Bc = Bn; Bn = tp;
            }
            compute16(Ac, Bc, acc, tx, ty);
            #pragma unroll
            for (int i = 0; i < 4; i++) {
                float4 w; w.x=acc[i][0]; w.y=acc[i][1]; w.z=acc[i][2]; w.w=acc[i][3];
                *(float4*)&g_W[(r0+ty*4+i)*DIM + c0 + tx*4] = w;
            }
        } else if (b < 88) {
            int i = (b-80)*64 + (t >> 2);
            int l4 = t & 3;
            const float* row = &g_V[i*NS];
            float s = 0.f;
            for (int k = l4*128; k < l4*128 + 128; k++) s += row[k]*f[k];
            s += __shfl_xor_sync(0xffffffffu, s, 1);
            s += __shfl_xor_sync(0xffffffffu, s, 2);
            if (l4 == 0) g_zv[i] = s + g_v[i];
        }
        gbar(++phase);

        // ============ P2: Q = C + F^T W (lower 55 tiles + mirror) ; q ; scalars ============
        if (b < 55) {
            int bi = 0, base = 0;
            while (base + bi + 1 <= b) { base += bi + 1; bi++; }
            int bj = b - base;
            int r0 = bi*64, c0 = bj*64;
            float* Ac = sh + SM_A0; float* Bc = sh + SM_B0;
            float* An = sh + SM_A1; float* Bn = sh + SM_B1;
            float4 va = *(const float4*)&F[l_kk*DIM + r0 + l_c4];
            float4 vb = *(const float4*)&g_W[l_kk*DIM + c0 + l_c4];
            *(float4*)&Ac[l_kk*68+l_c4] = va;
            *(float4*)&Bc[l_kk*64+l_c4] = vb;
            __syncthreads();
            float acc[4][4] = {};
            for (int k0 = 16; k0 < NS; k0 += 16) {
                va = *(const float4*)&F[(k0+l_kk)*DIM + r0 + l_c4];
                vb = *(const float4*)&g_W[(k0+l_kk)*DIM + c0 + l_c4];
                compute16(Ac, Bc, acc, tx, ty);
                *(float4*)&An[l_kk*68+l_c4] = va;
                *(float4*)&Bn[l_kk*64+l_c4] = vb;
                __syncthreads();
                float* tp;
                tp = Ac; Ac = An; An = tp;
                tp = Bc; Bc = Bn; Bn = tp;
            }
            compute16(Ac, Bc, acc, tx, ty);
            #pragma unroll
            for (int i = 0; i < 4; i++)
                #pragma unroll
                for (int j = 0; j < 4; j++) {
                    int gi = r0+ty*4+i, gj = c0+tx*4+j;
                    acc[i][j] += C[gi*DIM+gj];
                    g_Q[gi*DIM+gj] = acc[i][j];
                }
            if (bi != bj)
                mirror_tile(sh + SM_SCR, acc, tx, ty, t, g_Q, DIM, 0, 0, r0, c0);
        } else if (b < 65) {
            // q[o] = c[o] + sum_k F[k][o] * zv[k]   (coalesced along o)
            int o0 = (b-55)*64;
            int o = t & 63, sl = t >> 6;
            float s = 0.f;
            for (int k = sl*128; k < sl*128 + 128; k++)
                s += F[k*DIM + o0 + o] * g_zv[k];
            sh[sl*64 + o] = s;
            __syncthreads();
            if (t < 64)
                g_q[o0+t] = c[o0+t] + sh[t] + sh[64+t] + sh[128+t] + sh[192+t];
            __syncthreads();
        } else if (b == 65) {
            float s1 = 0.f, s2 = 0.f;
            for (int i = t; i < NS; i += NT) {
                float fi = f[i], vi = g_v[i];
                s1 += fi*(g_zv[i] - vi);
                s2 += fi*vi;
            }
            float* red = sh;
            red[t] = s1; __syncthreads();
            for (int st = 128; st > 0; st >>= 1) { if (t < st) red[t] += red[t+st]; __syncthreads(); }
            if (t == 0) g_fVf = red[0];
            __syncthreads();
            red[t] = s2; __syncthreads();
            for (int st = 128; st > 0; st >>= 1) { if (t < st) red[t] += red[t+st]; __syncthreads(); }
            if (t == 0) g_fv = red[0];
        }
        gbar(++phase);

        // ============ P3: Cholesky of Quu (CTA 0) ============
        if (b == 0) {
            float* shQ = sh;   // [128][129]
            for (int idx = t; idx < NC*NC; idx += NT)
                shQ[(idx>>7)*129 + (idx&127)] = g_Q[(NS+(idx>>7))*DIM + NS + (idx&127)];
            __syncthreads();
            for (int j = 0; j < NC; j++) {
                float d = shQ[j*129+j];
                float invs = rsqrtf(d);
                if (t < NC-j) shQ[(j+t)*129 + j] *= invs;
                if (t == 0) g_invd[j] = invs;
                __syncthreads();
                int i = j + 1 + (t >> 1);
                if (i < NC) {
                    float lij = shQ[i*129 + j];
                    int kbeg = j+1, kend = i;
                    int len = kend - kbeg + 1;
                    int mid = kbeg + ((len+1) >> 1);
                    int ka = (t&1) ? mid : kbeg;
                    int kb = (t&1) ? kend+1 : mid;
                    for (int k = ka; k < kb; k++)
                        shQ[i*129+k] -= lij * shQ[k*129+j];
                }
                __syncthreads();
            }
            for (int idx = t; idx < NC*NC; idx += NT) {
                int row = idx >> 7, col = idx & 127;
                if (col <= row) {
                    float val = shQ[row*129 + col];
                    g_Lsym[row*NC + col] = val;
                    g_Lsym[col*NC + row] = val;
                }
            }
        }
        gbar(++phase);

        // ============ P4: trsm -> K, k ============
        if (b < 65) {
            float* T      = sh;
            float* invd_s = sh + NC*NC;
            for (int idx = t; idx < NC*NC; idx += NT) T[idx] = g_Lsym[idx];
            if (t < NC) invd_s[t] = g_invd[t];
            __syncthreads();
            int warp = t >> 5, lane = t & 31;
            int col = b*8 + warp;
            if (col <= NS) {
                float r0, r1, r2, r3;
                if (col < NS) {
                    r0 = -g_Q[(NS+lane     )*DIM + col];
                    r1 = -g_Q[(NS+lane + 32)*DIM + col];
                    r2 = -g_Q[(NS+lane + 64)*DIM + col];
                    r3 = -g_Q[(NS+lane + 96)*DIM + col];
                } else {
                    r0 = -g_q[NS+lane]; r1 = -g_q[NS+lane+32];
                    r2 = -g_q[NS+lane+64]; r3 = -g_q[NS+lane+96];
                }
                #pragma unroll 1
                for (int i = 0; i < NC; i++) {
                    int si = i >> 5, li = i & 31;
                    float mv = (si == 0) ? r0 : ((si == 1) ? r1 : ((si == 2) ? r2 : r3));
                    float y = __shfl_sync(0xffffffffu, mv, li) * invd_s[i];
                    const float* Ti = T + i*NC;
                    if (lane      > i) r0 -= Ti[lane     ]*y; else if (lane      == i) r0 = y;
                    if (lane + 32 > i) r1 -= Ti[lane + 32]*y; else if (lane + 32 == i) r1 = y;
                    if (lane + 64 > i) r2 -= Ti[lane + 64]*y; else if (lane + 64 == i) r2 = y;
                    if (lane + 96 > i) r3 -= Ti[lane + 96]*y; else if (lane + 96 == i) r3 = y;
                }
                #pragma unroll 1
                for (int i = NC-1; i >= 0; i--) {
                    int si = i >> 5, li = i & 31;
                    float mv = (si == 0) ? r0 : ((si == 1) ? r1 : ((si == 2) ? r2 : r3));
                    float x = __shfl_sync(0xffffffffu, mv, li) * invd_s[i];
                    const float* Ti = T + i*NC;
                    if (lane      < i) r0 -= Ti[lane     ]*x; else if (lane      == i) r0 = x;
                    if (lane + 32 < i) r1 -= Ti[lane + 32]*x; else if (lane + 32 == i) r1 = x;
                    if (lane + 64 < i) r2 -= Ti[lane + 64]*x; else if (lane + 64 == i) r2 = x;
                    if (lane + 96 < i) r3 -= Ti[lane + 96]*x; else if (lane + 96 == i) r3 = x;
                }
                if (col < NS) {
                    float* Ko = Ks_all + (size_t)slot*NC*NS;
                    g_K[(lane     )*NS + col] = r0;  Ko[(lane     )*NS + col] = r0;
                    g_K[(lane + 32)*NS + col] = r1;  Ko[(lane + 32)*NS + col] = r1;
                    g_K[(lane + 64)*NS + col] = r2;  Ko[(lane + 64)*NS + col] = r2;
                    g_K[(lane + 96)*NS + col] = r3;  Ko[(lane + 96)*NS + col] = r3;
                } else {
                    float* ko = ks_all + (size_t)slot*NC;
                    g_k[lane]      = r0;  ko[lane]      = r0;
                    g_k[lane + 32] = r1;  ko[lane + 32] = r1;
                    g_k[lane + 64] = r2;  ko[lane + 64] = r2;
                    g_k[lane + 96] = r3;  ko[lane + 96] = r3;
                }
            }
        }
        gbar(++phase);

        // ============ P5: Vn = Qxx + Qxu K (lower 36 tiles + mirror) ; vn ; delta ============
        if (b < 36) {
            int bi = 0, base = 0;
            while (base + bi + 1 <= b) { base += bi + 1; bi++; }
            int bj = b - base;
            int r0 = bi*64, c0 = bj*64;
            float* Ac = sh + SM_A0; float* Bc = sh + SM_B0;
            float* An = sh + SM_A1; float* Bn = sh + SM_B1;
            float4 va = *(const float4*)&g_Q[(r0+l_row)*DIM + NS + l_k4];
            float4 vb = *(const float4*)&g_K[l_kk*NS + c0 + l_c4];
            Ac[(l_k4+0)*68+l_row]=va.x; Ac[(l_k4+1)*68+l_row]=va.y;
            Ac[(l_k4+2)*68+l_row]=va.z; Ac[(l_k4+3)*68+l_row]=va.w;
            *(float4*)&Bc[l_kk*64+l_c4] = vb;
            __syncthreads();
            float acc[4][4] = {};
            for (int k0 = 16; k0 < NC; k0 += 16) {
                va = *(const float4*)&g_Q[(r0+l_row)*DIM + NS + k0 + l_k4];
                vb = *(const float4*)&g_K[(k0+l_kk)*NS + c0 + l_c4];
                compute16(Ac, Bc, acc, tx, ty);
                An[(l_k4+0)*68+l_row]=va.x; An[(l_k4+1)*68+l_row]=va.y;
                An[(l_k4+2)*68+l_row]=va.z; An[(l_k4+3)*68+l_row]=va.w;
                *(float4*)&Bn[l_kk*64+l_c4] = vb;
                __syncthreads();
                float* tp;
                tp = Ac; Ac = An; An = tp;
                tp = Bc; Bc = Bn; Bn = tp;
            }
            compute16(Ac, Bc, acc, tx, ty);
            float* Vo = Vs_all + (size_t)slot*NS*NS;
            #pragma unroll
            for (int i = 0; i < 4; i++)
                #pragma unroll
                for (int j = 0; j < 4; j++) {
                    int gi = r0+ty*4+i, gj = c0+tx*4+j;
                    acc[i][j] += g_Q[gi*DIM+gj];
                    g_V[gi*NS+gj] = acc[i][j];
                    Vo[(size_t)gi*NS+gj] = acc[i][j];
                }
            if (bi != bj)
                mirror_tile(sh + SM_SCR, acc, tx, ty, t, g_V, NS, Vo, NS, r0, c0);
        } else if (b < 44) {
            int i = (b-36)*64 + (t >> 2);
            int l4 = t & 3;
            const float* row = &g_Q[i*DIM + NS];
            float s = 0.f;
            for (int a = l4*32; a < l4*32 + 32; a++) s += row[a]*g_k[a];
            s += __shfl_xor_sync(0xffffffffu, s, 1);
            s += __shfl_xor_sync(0xffffffffu, s, 2);
            if (l4 == 0) {
                float val = g_q[i] + s;
                g_v[i] = val;
                vs_all[(size_t)slot*NS + i] = val;
            }
        } else if (b == 44) {
            float* red = sh;
            float s = (t < NC) ? g_k[t]*g_q[NS+t] : 0.f;
            red[t] = s; __syncthreads();
            for (int st = 128; st > 0; st >>= 1) { if (t < st) red[t] += red[t+st]; __syncthreads(); }
            if (t == 0) g_delta[step] = 0.5f*red[0] + 0.5f*g_fVf + g_fv;
        }
        gbar(++phase);
    }

    if (b == 0 && t == 0) {
        float run = 0.f;
        for (int i = 0; i < HOR; i++) {
            run += g_delta[i];
            co_all[HOR-1-i] = run;
        }
    }
}

extern "C" void kernel_launch(void* const* d_in, const int* in_sizes, int n_in,
                              void* d_out, int out_size) {
    const float* F = (const float*)d_in[0];
    const float* f = (const float*)d_in[1];
    const float* C = (const float*)d_in[2];
    const float* c = (const float*)d_in[3];
    float* out = (float*)d_out;

    const int SMEM = 128*129*4;   // 66048 B (chol/trsm footprint; GEMM uses < 34KB)
    cudaFuncSetAttribute(lqr_persistent, cudaFuncAttributeMaxDynamicSharedMemorySize, SMEM);

    lqr_persistent<<<NB, NT, SMEM>>>(F, f, C, c, out);
}

// round 14
// speedup vs baseline: 1.5607x; 1.5607x over previous
#include <cuda_runtime.h>

#define NS 512
#define NC 128
#define DIM 640
#define HOR 256
#define NB 148
#define NT 256

// ---------------- device scratch ----------------
static __device__ float g_V[NS*NS];
static __device__ float g_v[NS];
static __device__ float g_W[NS*DIM];      // W = V * F
static __device__ float g_Q[DIM*DIM];
static __device__ float g_q[DIM];
static __device__ float g_zv[NS];         // V f + v
static __device__ float g_Lsym[NC*NC];
static __device__ float g_invd[NC];
static __device__ float g_K[NC*NS];
static __device__ float g_k[NC];
static __device__ float g_fVf, g_fv;
static __device__ float g_delta[HOR];
static __device__ unsigned g_count = 0;
static __device__ unsigned g_sense = 0;

// smem float offsets: 3 pipeline buffers, each A[16*68] + B[16*64]
#define BUFW 2112                 // words per buffer (1088 A + 1024 B)
#define SM_SCR (3*BUFW)           // 6336: 64*68 transpose scratch
// chol/trsm reuse sh[0 .. 128*129+128)

__device__ __forceinline__ void gbar(unsigned ph) {
    __syncthreads();
    if (threadIdx.x == 0) {
        __threadfence();
        if (atomicAdd(&g_count, 1u) == NB - 1u) {
            g_count = 0u;
            __threadfence();
            atomicExch(&g_sense, ph);
        } else {
            while (*(volatile unsigned*)&g_sense != ph) { }
            __threadfence();
        }
    }
    __syncthreads();
}

#define CP4(dst, src)  asm volatile("cp.async.ca.shared.global [%0], [%1], 4;"  :: "r"(dst), "l"(src))
#define CP16(dst, src) asm volatile("cp.async.cg.shared.global [%0], [%1], 16;" :: "r"(dst), "l"(src))
#define CPCOMMIT()     asm volatile("cp.async.commit_group;" ::)
#define CPWAIT(n)      asm volatile("cp.async.wait_group %0;" :: "n"(n))

#define MM16(av,bv) \
    acc[0][0] += av.x*bv.x; acc[0][1] += av.x*bv.y; acc[0][2] += av.x*bv.z; acc[0][3] += av.x*bv.w; \
    acc[1][0] += av.y*bv.x; acc[1][1] += av.y*bv.y; acc[1][2] += av.y*bv.z; acc[1][3] += av.y*bv.w; \
    acc[2][0] += av.z*bv.x; acc[2][1] += av.z*bv.y; acc[2][2] += av.z*bv.z; acc[2][3] += av.z*bv.w; \
    acc[3][0] += av.w*bv.x; acc[3][1] += av.w*bv.y; acc[3][2] += av.w*bv.z; acc[3][3] += av.w*bv.w;

__device__ __forceinline__ void compute16(const float* __restrict__ As,
                                          const float* __restrict__ Bs,
                                          float acc[4][4], int tx, int ty) {
    #pragma unroll
    for (int k2 = 0; k2 < 16; k2++) {
        float4 av = *(const float4*)&As[k2*68 + ty*4];
        float4 bv = *(const float4*)&Bs[k2*64 + tx*4];
        MM16(av, bv)
    }
}

// mirror a 64x64 tile of final values (held in acc) to the transposed location(s)
__device__ __forceinline__ void mirror_tile(float* scr, const float acc[4][4],
                                            int tx, int ty, int t,
                                            float* dst0, int ld0, float* dst1, int ld1,
                                            int r0, int c0) {
    #pragma unroll
    for (int i = 0; i < 4; i++) {
        float4 w; w.x = acc[i][0]; w.y = acc[i][1]; w.z = acc[i][2]; w.w = acc[i][3];
        *(float4*)&scr[(ty*4+i)*68 + tx*4] = w;
    }
    __syncthreads();
    int j = t >> 2, i4 = (t & 3)*16;
    #pragma unroll
    for (int m = 0; m < 4; m++) {
        float4 w;
        w.x = scr[(i4+4*m+0)*68 + j];
        w.y = scr[(i4+4*m+1)*68 + j];
        w.z = scr[(i4+4*m+2)*68 + j];
        w.w = scr[(i4+4*m+3)*68 + j];
        *(float4*)&dst0[(size_t)(c0+j)*ld0 + r0 + i4 + 4*m] = w;
        if (dst1) *(float4*)&dst1[(size_t)(c0+j)*ld1 + r0 + i4 + 4*m] = w;
    }
    __syncthreads();
}

__global__ __launch_bounds__(NT, 1)
void lqr_persistent(const float* __restrict__ F, const float* __restrict__ f,
                    const float* __restrict__ C, const float* __restrict__ c,
                    float* __restrict__ out) {
    extern __shared__ float sh[];
    const unsigned shb = (unsigned)__cvta_generic_to_shared(sh);
    const int b = blockIdx.x;
    const int t = threadIdx.x;
    const int tx = t & 15, ty = t >> 4;

    float* Ks_all = out;
    float* ks_all = out + (size_t)HOR*NC*NS;
    float* Vs_all = ks_all + (size_t)HOR*NC;
    float* vs_all = Vs_all + (size_t)HOR*NS*NS;
    float* co_all = vs_all + (size_t)HOR*NS;

    unsigned phase = *(volatile unsigned*)&g_sense;

    // ---- init ----
    for (int idx = b*NT + t; idx < NS*NS; idx += NB*NT)
        g_V[idx] = C[(idx >> 9)*DIM + (idx & 511)];
    for (int idx = b*NT + t; idx < NS; idx += NB*NT)
        g_v[idx] = c[idx];
    gbar(++phase);

    // loader index precompute
    const int l_row = t >> 2, l_k4 = (t & 3) << 2;       // transpose-A loader (4B copies)
    const int l_kk  = t >> 4, l_c4 = (t & 15) << 2;      // direct 16B loader

    for (int step = 0; step < HOR; step++) {
        const int slot = HOR - 1 - step;

        // ============ P1: W = V*F (8x10 tiles) ; zv ============
        if (b < 80) {
            int r0 = (b/10)*64, c0 = (b%10)*64;
            // async loaders: A = V (transposed into smem), B = F (direct)
            #define P1_LOAD(bi_, k0_) { \
                const float* sa_ = &g_V[(size_t)(r0+l_row)*NS + (k0_) + l_k4]; \
                CP4(shb + (((bi_)*BUFW + (l_k4+0)*68 + l_row) << 2), sa_+0); \
                CP4(shb + (((bi_)*BUFW + (l_k4+1)*68 + l_row) << 2), sa_+1); \
                CP4(shb + (((bi_)*BUFW + (l_k4+2)*68 + l_row) << 2), sa_+2); \
                CP4(shb + (((bi_)*BUFW + (l_k4+3)*68 + l_row) << 2), sa_+3); \
                CP16(shb + (((bi_)*BUFW + 1088 + l_kk*64 + l_c4) << 2), \
                     &F[(size_t)((k0_)+l_kk)*DIM + c0 + l_c4]); \
                CPCOMMIT(); }
            P1_LOAD(0, 0)
            P1_LOAD(1, 16)
            float acc[4][4] = {};
            #pragma unroll 1
            for (int s = 0; s < 32; s++) {
                if (s < 31) { CPWAIT(1); } else { CPWAIT(0); }
                __syncthreads();
                if (s + 2 < 32) {
                    int bi = (s+2)%3, k0 = (s+2)*16;
                    P1_LOAD(bi, k0)
                }
                int cb = s % 3;
                compute16(sh + cb*BUFW, sh + cb*BUFW + 1088, acc, tx, ty);
            }
            #pragma unroll
            for (int i = 0; i < 4; i++) {
                float4 w; w.x=acc[i][0]; w.y=acc[i][1]; w.z=acc[i][2]; w.w=acc[i][3];
                *(float4*)&g_W[(size_t)(r0+ty*4+i)*DIM + c0 + tx*4] = w;
            }
            #undef P1_LOAD
        } else if (b < 88) {
            int i = (b-80)*64 + (t >> 2);
            int l4 = t & 3;
            const float* row = &g_V[(size_t)i*NS];
            float s = 0.f;
            for (int k = l4*128; k < l4*128 + 128; k++) s += row[k]*f[k];
            s += __shfl_xor_sync(0xffffffffu, s, 1);
            s += __shfl_xor_sync(0xffffffffu, s, 2);
            if (l4 == 0) g_zv[i] = s + g_v[i];
        }
        gbar(++phase);

        // ============ P2: Q = C + F^T W (lower 55 tiles + mirror) ; q ; scalars ============
        if (b < 55) {
            int bi = 0, base = 0;
            while (base + bi + 1 <= b) { base += bi + 1; bi++; }
            int bj = b - base;
            int r0 = bi*64, c0 = bj*64;
            // A = F (direct, columns r0..), B = W (direct)
            #define P2_LOAD(bi_, k0_) { \
                CP16(shb + (((bi_)*BUFW + l_kk*68 + l_c4) << 2), \
                     &F[(size_t)((k0_)+l_kk)*DIM + r0 + l_c4]); \
                CP16(shb + (((bi_)*BUFW + 1088 + l_kk*64 + l_c4) << 2), \
                     &g_W[(size_t)((k0_)+l_kk)*DIM + c0 + l_c4]); \
                CPCOMMIT(); }
            P2_LOAD(0, 0)
            P2_LOAD(1, 16)
            float acc[4][4] = {};
            #pragma unroll 1
            for (int s = 0; s < 32; s++) {
                if (s < 31) { CPWAIT(1); } else { CPWAIT(0); }
                __syncthreads();
                if (s + 2 < 32) {
                    int bb = (s+2)%3, k0 = (s+2)*16;
                    P2_LOAD(bb, k0)
                }
                int cb = s % 3;
                compute16(sh + cb*BUFW, sh + cb*BUFW + 1088, acc, tx, ty);
            }
            #pragma unroll
            for (int i = 0; i < 4; i++)
                #pragma unroll
                for (int j = 0; j < 4; j++) {
                    int gi = r0+ty*4+i, gj = c0+tx*4+j;
                    acc[i][j] += C[(size_t)gi*DIM+gj];
                    g_Q[(size_t)gi*DIM+gj] = acc[i][j];
                }
            if (bi != bj)
                mirror_tile(sh + SM_SCR, acc, tx, ty, t, g_Q, DIM, 0, 0, r0, c0);
            #undef P2_LOAD
        } else if (b < 65) {
            // q[o] = c[o] + sum_k F[k][o] * zv[k]   (coalesced along o)
            int o0 = (b-55)*64;
            int o = t & 63, sl = t >> 6;
            float s = 0.f;
            for (int k = sl*128; k < sl*128 + 128; k++)
                s += F[(size_t)k*DIM + o0 + o] * g_zv[k];
            sh[sl*64 + o] = s;
            __syncthreads();
            if (t < 64)
                g_q[o0+t] = c[o0+t] + sh[t] + sh[64+t] + sh[128+t] + sh[192+t];
            __syncthreads();
        } else if (b == 65) {
            float s1 = 0.f, s2 = 0.f;
            for (int i = t; i < NS; i += NT) {
                float fi = f[i], vi = g_v[i];
                s1 += fi*(g_zv[i] - vi);
                s2 += fi*vi;
            }
            float* red = sh;
            red[t] = s1; __syncthreads();
            for (int st = 128; st > 0; st >>= 1) { if (t < st) red[t] += red[t+st]; __syncthreads(); }
            if (t == 0) g_fVf = red[0];
            __syncthreads();
            red[t] = s2; __syncthreads();
            for (int st = 128; st > 0; st >>= 1) { if (t < st) red[t] += red[t+st]; __syncthreads(); }
            if (t == 0) g_fv = red[0];
        }
        gbar(++phase);

        // ============ P3: Cholesky of Quu (CTA 0) ============
        if (b == 0) {
            float* shQ = sh;   // [128][129]
            for (int idx = t; idx < NC*NC; idx += NT)
                shQ[(idx>>7)*129 + (idx&127)] = g_Q[(size_t)(NS+(idx>>7))*DIM + NS + (idx&127)];
            __syncthreads();
            for (int j = 0; j < NC; j++) {
                float d = shQ[j*129+j];
                float invs = rsqrtf(d);
                if (t < NC-j) shQ[(j+t)*129 + j] *= invs;
                if (t == 0) g_invd[j] = invs;
                __syncthreads();
                int i = j + 1 + (t >> 1);
                if (i < NC) {
                    float lij = shQ[i*129 + j];
                    int kbeg = j+1, kend = i;
                    int len = kend - kbeg + 1;
                    int mid = kbeg + ((len+1) >> 1);
                    int ka = (t&1) ? mid : kbeg;
                    int kb = (t&1) ? kend+1 : mid;
                    for (int k = ka; k < kb; k++)
                        shQ[i*129+k] -= lij * shQ[k*129+j];
                }
                __syncthreads();
            }
            for (int idx = t; idx < NC*NC; idx += NT) {
                int row = idx >> 7, col = idx & 127;
                if (col <= row) {
                    float val = shQ[row*129 + col];
                    g_Lsym[row*NC + col] = val;
                    g_Lsym[col*NC + row] = val;
                }
            }
        }
        gbar(++phase);

        // ============ P4: trsm -> K, k ============
        if (b < 65) {
            float* T      = sh;
            float* invd_s = sh + NC*NC;
            for (int idx = t; idx < NC*NC; idx += NT) T[idx] = g_Lsym[idx];
            if (t < NC) invd_s[t] = g_invd[t];
            __syncthreads();
            int warp = t >> 5, lane = t & 31;
            int col = b*8 + warp;
            if (col <= NS) {
                float r0, r1, r2, r3;
                if (col < NS) {
                    r0 = -g_Q[(size_t)(NS+lane     )*DIM + col];
                    r1 = -g_Q[(size_t)(NS+lane + 32)*DIM + col];
                    r2 = -g_Q[(size_t)(NS+lane + 64)*DIM + col];
                    r3 = -g_Q[(size_t)(NS+lane + 96)*DIM + col];
                } else {
                    r0 = -g_q[NS+lane]; r1 = -g_q[NS+lane+32];
                    r2 = -g_q[NS+lane+64]; r3 = -g_q[NS+lane+96];
                }
                #pragma unroll 1
                for (int i = 0; i < NC; i++) {
                    int si = i >> 5, li = i & 31;
                    float mv = (si == 0) ? r0 : ((si == 1) ? r1 : ((si == 2) ? r2 : r3));
                    float y = __shfl_sync(0xffffffffu, mv, li) * invd_s[i];
                    const float* Ti = T + i*NC;
                    if (lane      > i) r0 -= Ti[lane     ]*y; else if (lane      == i) r0 = y;
                    if (lane + 32 > i) r1 -= Ti[lane + 32]*y; else if (lane + 32 == i) r1 = y;
                    if (lane + 64 > i) r2 -= Ti[lane + 64]*y; else if (lane + 64 == i) r2 = y;
                    if (lane + 96 > i) r3 -= Ti[lane + 96]*y; else if (lane + 96 == i) r3 = y;
                }
                #pragma unroll 1
                for (int i = NC-1; i >= 0; i--) {
                    int si = i >> 5, li = i & 31;
                    float mv = (si == 0) ? r0 : ((si == 1) ? r1 : ((si == 2) ? r2 : r3));
                    float x = __shfl_sync(0xffffffffu, mv, li) * invd_s[i];
                    const float* Ti = T + i*NC;
                    if (lane      < i) r0 -= Ti[lane     ]*x; else if (lane      == i) r0 = x;
                    if (lane + 32 < i) r1 -= Ti[lane + 32]*x; else if (lane + 32 == i) r1 = x;
                    if (lane + 64 < i) r2 -= Ti[lane + 64]*x; else if (lane + 64 == i) r2 = x;
                    if (lane + 96 < i) r3 -= Ti[lane + 96]*x; else if (lane + 96 == i) r3 = x;
                }
                if (col < NS) {
                    float* Ko = Ks_all + (size_t)slot*NC*NS;
                    g_K[(lane     )*NS + col] = r0;  Ko[(lane     )*NS + col] = r0;
                    g_K[(lane + 32)*NS + col] = r1;  Ko[(lane + 32)*NS + col] = r1;
                    g_K[(lane + 64)*NS + col] = r2;  Ko[(lane + 64)*NS + col] = r2;
                    g_K[(lane + 96)*NS + col] = r3;  Ko[(lane + 96)*NS + col] = r3;
                } else {
                    float* ko = ks_all + (size_t)slot*NC;
                    g_k[lane]      = r0;  ko[lane]      = r0;
                    g_k[lane + 32] = r1;  ko[lane + 32] = r1;
                    g_k[lane + 64] = r2;  ko[lane + 64] = r2;
                    g_k[lane + 96] = r3;  ko[lane + 96] = r3;
                }
            }
        }
        gbar(++phase);

        // ============ P5: Vn = Qxx + Qxu K (lower 36 tiles + mirror) ; vn ; delta ============
        if (b < 36) {
            int bi = 0, base = 0;
            while (base + bi + 1 <= b) { base += bi + 1; bi++; }
            int bj = b - base;
            int r0 = bi*64, c0 = bj*64;
            // A = Qxu (transposed into smem), B = K (direct)
            #define P5_LOAD(bi_, k0_) { \
                const float* sa_ = &g_Q[(size_t)(r0+l_row)*DIM + NS + (k0_) + l_k4]; \
                CP4(shb + (((bi_)*BUFW + (l_k4+0)*68 + l_row) << 2), sa_+0); \
                CP4(shb + (((bi_)*BUFW + (l_k4+1)*68 + l_row) << 2), sa_+1); \
                CP4(shb + (((bi_)*BUFW + (l_k4+2)*68 + l_row) << 2), sa_+2); \
                CP4(shb + (((bi_)*BUFW + (l_k4+3)*68 + l_row) << 2), sa_+3); \
                CP16(shb + (((bi_)*BUFW + 1088 + l_kk*64 + l_c4) << 2), \
                     &g_K[(size_t)((k0_)+l_kk)*NS + c0 + l_c4]); \
                CPCOMMIT(); }
            P5_LOAD(0, 0)
            P5_LOAD(1, 16)
            float acc[4][4] = {};
            #pragma unroll 1
            for (int s = 0; s < 8; s++) {
                if (s < 7) { CPWAIT(1); } else { CPWAIT(0); }
                __syncthreads();
                if (s + 2 < 8) {
                    int bb = (s+2)%3, k0 = (s+2)*16;
                    P5_LOAD(bb, k0)
                }
                int cb = s % 3;
                compute16(sh + cb*BUFW, sh + cb*BUFW + 1088, acc, tx, ty);
            }
            float* Vo = Vs_all + (size_t)slot*NS*NS;
            #pragma unroll
            for (int i = 0; i < 4; i++)
                #pragma unroll
                for (int j = 0; j < 4; j++) {
                    int gi = r0+ty*4+i, gj = c0+tx*4+j;
                    acc[i][j] += g_Q[(size_t)gi*DIM+gj];
                    g_V[(size_t)gi*NS+gj] = acc[i][j];
                    Vo[(size_t)gi*NS+gj] = acc[i][j];
                }
            if (bi != bj)
                mirror_tile(sh + SM_SCR, acc, tx, ty, t, g_V, NS, Vo, NS, r0, c0);
            #undef P5_LOAD
        } else if (b < 44) {
            int i = (b-36)*64 + (t >> 2);
            int l4 = t & 3;
            const float* row = &g_Q[(size_t)i*DIM + NS];
            float s = 0.f;
            for (int a = l4*32; a < l4*32 + 32; a++) s += row[a]*g_k[a];
            s += __shfl_xor_sync(0xffffffffu, s, 1);
            s += __shfl_xor_sync(0xffffffffu, s, 2);
            if (l4 == 0) {
                float val = g_q[i] + s;
                g_v[i] = val;
                vs_all[(size_t)slot*NS + i] = val;
            }
        } else if (b == 44) {
            float* red = sh;
            float s = (t < NC) ? g_k[t]*g_q[NS+t] : 0.f;
            red[t] = s; __syncthreads();
            for (int st = 128; st > 0; st >>= 1) { if (t < st) red[t] += red[t+st]; __syncthreads(); }
            if (t == 0) g_delta[step] = 0.5f*red[0] + 0.5f*g_fVf + g_fv;
        }
        gbar(++phase);
    }

    if (b == 0 && t == 0) {
        float run = 0.f;
        for (int i = 0; i < HOR; i++) {
            run += g_delta[i];
            co_all[HOR-1-i] = run;
        }
    }
}

extern "C" void kernel_launch(void* const* d_in, const int* in_sizes, int n_in,
                              void* d_out, int out_size) {
    const float* F = (const float*)d_in[0];
    const float* f = (const float*)d_in[1];
    const float* C = (const float*)d_in[2];
    const float* c = (const float*)d_in[3];
    float* out = (float*)d_out;

    const int SMEM = 128*129*4;   // 66048 B (chol/trsm footprint; GEMM pipeline uses ~43KB)
    cudaFuncSetAttribute(lqr_persistent, cudaFuncAttributeMaxDynamicSharedMemorySize, SMEM);

    lqr_persistent<<<NB, NT, SMEM>>>(F, f, C, c, out);
}

// round 17
// speedup vs baseline: 1.6767x; 1.0743x over previous
#include <cuda_runtime.h>

#define NS 512
#define NC 128
#define DIM 640
#define HOR 256
#define NB 148
#define NT 512

// ---------------- device scratch ----------------
static __device__ float g_V[NS*NS];
static __device__ float g_v[NS];
static __device__ float g_W[NS*DIM];      // W = V * F
static __device__ float g_Q[DIM*DIM];
static __device__ float g_q[DIM];
static __device__ float g_zv[NS];         // V f + v
static __device__ float g_Lsym[NC*NC];
static __device__ float g_invd[NC];
static __device__ float g_K[NC*NS];
static __device__ float g_k[NC];
static __device__ float g_fVf, g_fv;
static __device__ float g_delta[HOR];
static __device__ unsigned g_count = 0;
static __device__ unsigned g_sense = 0;

// smem float offsets: 3 pipeline buffers, each A[16*68] + B[16*64]
#define BUFW 2112                 // words per buffer (1088 A + 1024 B)
#define SM_SCR (3*BUFW)           // 6336: 64*68 transpose scratch
// chol/trsm reuse sh[0 .. 128*129+128)

__device__ __forceinline__ void gbar(unsigned ph) {
    __syncthreads();
    if (threadIdx.x == 0) {
        __threadfence();
        if (atomicAdd(&g_count, 1u) == NB - 1u) {
            g_count = 0u;
            __threadfence();
            atomicExch(&g_sense, ph);
        } else {
            while (*(volatile unsigned*)&g_sense != ph) { }
            __threadfence();
        }
    }
    __syncthreads();
}

#define CP4(dst, src)  asm volatile("cp.async.ca.shared.global [%0], [%1], 4;"  :: "r"(dst), "l"(src))
#define CP16(dst, src) asm volatile("cp.async.cg.shared.global [%0], [%1], 16;" :: "r"(dst), "l"(src))
#define CPCOMMIT()     asm volatile("cp.async.commit_group;" ::)
#define CPWAIT(n)      asm volatile("cp.async.wait_group %0;" :: "n"(n))

// 4x2 microtile: ty = t>>5 (warp id, 16 warps -> 64 rows), tx = t&31 (-> 64 cols)
// A read is warp-uniform (broadcast LDS.128); B is conflict-free LDS.64.
__device__ __forceinline__ void compute16(const float* __restrict__ As,
                                          const float* __restrict__ Bs,
                                          float acc[4][2], int tx, int ty) {
    #pragma unroll
    for (int k2 = 0; k2 < 16; k2++) {
        float4 av = *(const float4*)&As[k2*68 + ty*4];
        float2 bv = *(const float2*)&Bs[k2*64 + tx*2];
        acc[0][0] += av.x*bv.x; acc[0][1] += av.x*bv.y;
        acc[1][0] += av.y*bv.x; acc[1][1] += av.y*bv.y;
        acc[2][0] += av.z*bv.x; acc[2][1] += av.z*bv.y;
        acc[3][0] += av.w*bv.x; acc[3][1] += av.w*bv.y;
    }
}

// mirror a 64x64 tile of final values (held in acc) to the transposed location(s)
__device__ __forceinline__ void mirror_tile(float* scr, const float acc[4][2],
                                            int tx, int ty, int t,
                                            float* dst0, int ld0, float* dst1, int ld1,
                                            int r0, int c0) {
    #pragma unroll
    for (int i = 0; i < 4; i++) {
        float2 w; w.x = acc[i][0]; w.y = acc[i][1];
        *(float2*)&scr[(ty*4+i)*68 + tx*2] = w;
    }
    __syncthreads();
    int j = t >> 3, i8 = (t & 7)*8;
    #pragma unroll
    for (int m = 0; m < 2; m++) {
        float4 w;
        w.x = scr[(i8+4*m+0)*68 + j];
        w.y = scr[(i8+4*m+1)*68 + j];
        w.z = scr[(i8+4*m+2)*68 + j];
        w.w = scr[(i8+4*m+3)*68 + j];
        *(float4*)&dst0[(size_t)(c0+j)*ld0 + r0 + i8 + 4*m] = w;
        if (dst1) *(float4*)&dst1[(size_t)(c0+j)*ld1 + r0 + i8 + 4*m] = w;
    }
    __syncthreads();
}

__global__ __launch_bounds__(NT, 1)
void lqr_persistent(const float* __restrict__ F, const float* __restrict__ f,
                    const float* __restrict__ C, const float* __restrict__ c,
                    float* __restrict__ out) {
    extern __shared__ float sh[];
    const unsigned shb = (unsigned)__cvta_generic_to_shared(sh);
    const int b = blockIdx.x;
    const int t = threadIdx.x;
    const int tx = t & 31, ty = t >> 5;

    float* Ks_all = out;
    float* ks_all = out + (size_t)HOR*NC*NS;
    float* Vs_all = ks_all + (size_t)HOR*NC;
    float* vs_all = Vs_all + (size_t)HOR*NS*NS;
    float* co_all = vs_all + (size_t)HOR*NS;

    unsigned phase = *(volatile unsigned*)&g_sense;

    // ---- init ----
    for (int idx = b*NT + t; idx < NS*NS; idx += NB*NT)
        g_V[idx] = C[(idx >> 9)*DIM + (idx & 511)];
    for (int idx = b*NT + t; idx < NS; idx += NB*NT)
        g_v[idx] = c[idx];
    gbar(++phase);

    // loader index precompute
    const int l_row = t >> 3, l_k2 = (t & 7) << 1;       // transpose-A loader (2x CP4, 512 thr)
    const int l_kk  = (t & 255) >> 4, l_c4 = (t & 15) << 2;  // 16B loader (per 256-thread half)

    for (int step = 0; step < HOR; step++) {
        const int slot = HOR - 1 - step;

        // ============ P1: W = V*F (8x10 tiles) ; zv ============
        if (b < 80) {
            int r0 = (b/10)*64, c0 = (b%10)*64;
            // A = V (transposed into smem, all 512 thr), B = F (direct, thr < 256)
            #define P1_LOAD(bi_, k0_) { \
                const float* sa_ = &g_V[(size_t)(r0+l_row)*NS + (k0_) + l_k2]; \
                CP4(shb + (((bi_)*BUFW + (l_k2+0)*68 + l_row) << 2), sa_+0); \
                CP4(shb + (((bi_)*BUFW + (l_k2+1)*68 + l_row) << 2), sa_+1); \
                if (t < 256) CP16(shb + (((bi_)*BUFW + 1088 + l_kk*64 + l_c4) << 2), \
                     &F[(size_t)((k0_)+l_kk)*DIM + c0 + l_c4]); \
                CPCOMMIT(); }
            P1_LOAD(0, 0)
            P1_LOAD(1, 16)
            float acc[4][2] = {};
            #pragma unroll 1
            for (int s = 0; s < 32; s++) {
                if (s < 31) { CPWAIT(1); } else { CPWAIT(0); }
                __syncthreads();
                if (s + 2 < 32) {
                    int bi = (s+2)%3, k0 = (s+2)*16;
                    P1_LOAD(bi, k0)
                }
                int cb = s % 3;
                compute16(sh + cb*BUFW, sh + cb*BUFW + 1088, acc, tx, ty);
            }
            #pragma unroll
            for (int i = 0; i < 4; i++) {
                float2 w; w.x=acc[i][0]; w.y=acc[i][1];
                *(float2*)&g_W[(size_t)(r0+ty*4+i)*DIM + c0 + tx*2] = w;
            }
            #undef P1_LOAD
        } else if (b < 88) {
            int i = (b-80)*64 + (t >> 3);
            int l8 = t & 7;
            const float* row = &g_V[(size_t)i*NS];
            float s = 0.f;
            for (int k = l8*64; k < l8*64 + 64; k++) s += row[k]*f[k];
            s += __shfl_xor_sync(0xffffffffu, s, 1);
            s += __shfl_xor_sync(0xffffffffu, s, 2);
            s += __shfl_xor_sync(0xffffffffu, s, 4);
            if (l8 == 0) g_zv[i] = s + g_v[i];
        }
        gbar(++phase);

        // ============ P2: Q = C + F^T W (lower 55 tiles + mirror) ; q ; scalars ============
        if (b < 55) {
            int bi = 0, base = 0;
            while (base + bi + 1 <= b) { base += bi + 1; bi++; }
            int bj = b - base;
            int r0 = bi*64, c0 = bj*64;
            // A = F (direct, thr < 256), B = W (direct, thr >= 256)
            #define P2_LOAD(bi_, k0_) { \
                if (t < 256) CP16(shb + (((bi_)*BUFW + l_kk*68 + l_c4) << 2), \
                     &F[(size_t)((k0_)+l_kk)*DIM + r0 + l_c4]); \
                else CP16(shb + (((bi_)*BUFW + 1088 + l_kk*64 + l_c4) << 2), \
                     &g_W[(size_t)((k0_)+l_kk)*DIM + c0 + l_c4]); \
                CPCOMMIT(); }
            P2_LOAD(0, 0)
            P2_LOAD(1, 16)
            float acc[4][2] = {};
            #pragma unroll 1
            for (int s = 0; s < 32; s++) {
                if (s < 31) { CPWAIT(1); } else { CPWAIT(0); }
                __syncthreads();
                if (s + 2 < 32) {
                    int bb = (s+2)%3, k0 = (s+2)*16;
                    P2_LOAD(bb, k0)
                }
                int cb = s % 3;
                compute16(sh + cb*BUFW, sh + cb*BUFW + 1088, acc, tx, ty);
            }
            #pragma unroll
            for (int i = 0; i < 4; i++)
                #pragma unroll
                for (int j = 0; j < 2; j++) {
                    int gi = r0+ty*4+i, gj = c0+tx*2+j;
                    acc[i][j] += C[(size_t)gi*DIM+gj];
                    g_Q[(size_t)gi*DIM+gj] = acc[i][j];
                }
            if (bi != bj)
                mirror_tile(sh + SM_SCR, acc, tx, ty, t, g_Q, DIM, 0, 0, r0, c0);
            #undef P2_LOAD
        } else if (b < 65) {
            // q[o] = c[o] + sum_k F[k][o] * zv[k]   (coalesced along o)
            int o0 = (b-55)*64;
            int o = t & 63, sl = t >> 6;         // 8 slices of 64 k
            float s = 0.f;
            for (int k = sl*64; k < sl*64 + 64; k++)
                s += F[(size_t)k*DIM + o0 + o] * g_zv[k];
            sh[sl*64 + o] = s;
            __syncthreads();
            if (t < 64) {
                float acc = c[o0+t];
                #pragma unroll
                for (int p = 0; p < 8; p++) acc += sh[p*64 + t];
                g_q[o0+t] = acc;
            }
            __syncthreads();
        } else if (b == 65) {
            float s1 = 0.f, s2 = 0.f;
            for (int i = t; i < NS; i += NT) {
                float fi = f[i], vi = g_v[i];
                s1 += fi*(g_zv[i] - vi);
                s2 += fi*vi;
            }
            float* red = sh;
            red[t] = s1; __syncthreads();
            for (int st = 256; st > 0; st >>= 1) { if (t < st) red[t] += red[t+st]; __syncthreads(); }
            if (t == 0) g_fVf = red[0];
            __syncthreads();
            red[t] = s2; __syncthreads();
            for (int st = 256; st > 0; st >>= 1) { if (t < st) red[t] += red[t+st]; __syncthreads(); }
            if (t == 0) g_fv = red[0];
        }
        gbar(++phase);

        // ============ P3: Cholesky of Quu (CTA 0, 4 threads/row) ============
        if (b == 0) {
            float* shQ = sh;   // [128][129]
            for (int idx = t; idx < NC*NC; idx += NT)
                shQ[(idx>>7)*129 + (idx&127)] = g_Q[(size_t)(NS+(idx>>7))*DIM + NS + (idx&127)];
            __syncthreads();
            for (int j = 0; j < NC; j++) {
                float d = shQ[j*129+j];
                float invs = rsqrtf(d);
                if (t < NC-j) shQ[(j+t)*129 + j] *= invs;
                if (t == 0) g_invd[j] = invs;
                __syncthreads();
                int i = j + 1 + (t >> 2);
                if (i < NC) {
                    float lij = shQ[i*129 + j];
                    for (int k = j + 1 + (t & 3); k <= i; k += 4)
                        shQ[i*129+k] -= lij * shQ[k*129+j];
                }
                __syncthreads();
            }
            for (int idx = t; idx < NC*NC; idx += NT) {
                int row = idx >> 7, col = idx & 127;
                if (col <= row) {
                    float val = shQ[row*129 + col];
                    g_Lsym[row*NC + col] = val;
                    g_Lsym[col*NC + row] = val;
                }
            }
        }
        gbar(++phase);

        // ============ P4: trsm -> K, k (16 warps/CTA, 33 CTAs) ============
        if (b < 33) {
            float* T      = sh;
            float* invd_s = sh + NC*NC;
            for (int idx = t; idx < NC*NC; idx += NT) T[idx] = g_Lsym[idx];
            if (t < NC) invd_s[t] = g_invd[t];
            __syncthreads();
            int warp = t >> 5, lane = t & 31;
            int col = b*16 + warp;
            if (col <= NS) {
                float r0, r1, r2, r3;
                if (col < NS) {
                    r0 = -g_Q[(size_t)(NS+lane     )*DIM + col];
                    r1 = -g_Q[(size_t)(NS+lane + 32)*DIM + col];
                    r2 = -g_Q[(size_t)(NS+lane + 64)*DIM + col];
                    r3 = -g_Q[(size_t)(NS+lane + 96)*DIM + col];
                } else {
                    r0 = -g_q[NS+lane]; r1 = -g_q[NS+lane+32];
                    r2 = -g_q[NS+lane+64]; r3 = -g_q[NS+lane+96];
                }
                #pragma unroll 1
                for (int i = 0; i < NC; i++) {
                    int si = i >> 5, li = i & 31;
                    float mv = (si == 0) ? r0 : ((si == 1) ? r1 : ((si == 2) ? r2 : r3));
                    float y = __shfl_sync(0xffffffffu, mv, li) * invd_s[i];
                    const float* Ti = T + i*NC;
                    if (lane      > i) r0 -= Ti[lane     ]*y; else if (lane      == i) r0 = y;
                    if (lane + 32 > i) r1 -= Ti[lane + 32]*y; else if (lane + 32 == i) r1 = y;
                    if (lane + 64 > i) r2 -= Ti[lane + 64]*y; else if (lane + 64 == i) r2 = y;
                    if (lane + 96 > i) r3 -= Ti[lane + 96]*y; else if (lane + 96 == i) r3 = y;
                }
                #pragma unroll 1
                for (int i = NC-1; i >= 0; i--) {
                    int si = i >> 5, li = i & 31;
                    float mv = (si == 0) ? r0 : ((si == 1) ? r1 : ((si == 2) ? r2 : r3));
                    float x = __shfl_sync(0xffffffffu, mv, li) * invd_s[i];
                    const float* Ti = T + i*NC;
                    if (lane      < i) r0 -= Ti[lane     ]*x; else if (lane      == i) r0 = x;
                    if (lane + 32 < i) r1 -= Ti[lane + 32]*x; else if (lane + 32 == i) r1 = x;
                    if (lane + 64 < i) r2 -= Ti[lane + 64]*x; else if (lane + 64 == i) r2 = x;
                    if (lane + 96 < i) r3 -= Ti[lane + 96]*x; else if (lane + 96 == i) r3 = x;
                }
                if (col < NS) {
                    float* Ko = Ks_all + (size_t)slot*NC*NS;
                    g_K[(lane     )*NS + col] = r0;  Ko[(lane     )*NS + col] = r0;
                    g_K[(lane + 32)*NS + col] = r1;  Ko[(lane + 32)*NS + col] = r1;
                    g_K[(lane + 64)*NS + col] = r2;  Ko[(lane + 64)*NS + col] = r2;
                    g_K[(lane + 96)*NS + col] = r3;  Ko[(lane + 96)*NS + col] = r3;
                } else {
                    float* ko = ks_all + (size_t)slot*NC;
                    g_k[lane]      = r0;  ko[lane]      = r0;
                    g_k[lane + 32] = r1;  ko[lane + 32] = r1;
                    g_k[lane + 64] = r2;  ko[lane + 64] = r2;
                    g_k[lane + 96] = r3;  ko[lane + 96] = r3;
                }
            }
        }
        gbar(++phase);

        // ============ P5: Vn = Qxx + Qxu K (lower 36 tiles + mirror) ; vn ; delta ============
        if (b < 36) {
            int bi = 0, base = 0;
            while (base + bi + 1 <= b) { base += bi + 1; bi++; }
            int bj = b - base;
            int r0 = bi*64, c0 = bj*64;
            // A = Qxu (transposed into smem), B = K (direct, thr < 256)
            #define P5_LOAD(bi_, k0_) { \
                const float* sa_ = &g_Q[(size_t)(r0+l_row)*DIM + NS + (k0_) + l_k2]; \
                CP4(shb + (((bi_)*BUFW + (l_k2+0)*68 + l_row) << 2), sa_+0); \
                CP4(shb + (((bi_)*BUFW + (l_k2+1)*68 + l_row) << 2), sa_+1); \
                if (t < 256) CP16(shb + (((bi_)*BUFW + 1088 + l_kk*64 + l_c4) << 2), \
                     &g_K[(size_t)((k0_)+l_kk)*NS + c0 + l_c4]); \
                CPCOMMIT(); }
            P5_LOAD(0, 0)
            P5_LOAD(1, 16)
            float acc[4][2] = {};
            #pragma unroll 1
            for (int s = 0; s < 8; s++) {
                if (s < 7) { CPWAIT(1); } else { CPWAIT(0); }
                __syncthreads();
                if (s + 2 < 8) {
                    int bb = (s+2)%3, k0 = (s+2)*16;
                    P5_LOAD(bb, k0)
                }
                int cb = s % 3;
                compute16(sh + cb*BUFW, sh + cb*BUFW + 1088, acc, tx, ty);
            }
            float* Vo = Vs_all + (size_t)slot*NS*NS;
            #pragma unroll
            for (int i = 0; i < 4; i++)
                #pragma unroll
                for (int j = 0; j < 2; j++) {
                    int gi = r0+ty*4+i, gj = c0+tx*2+j;
                    acc[i][j] += g_Q[(size_t)gi*DIM+gj];
                    g_V[(size_t)gi*NS+gj] = acc[i][j];
                    Vo[(size_t)gi*NS+gj] = acc[i][j];
                }
            if (bi != bj)
                mirror_tile(sh + SM_SCR, acc, tx, ty, t, g_V, NS, Vo, NS, r0, c0);
            #undef P5_LOAD
        } else if (b < 44) {
            int i = (b-36)*64 + (t >> 3);
            int l8 = t & 7;
            const float* row = &g_Q[(size_t)i*DIM + NS];
            float s = 0.f;
            for (int a = l8*16; a < l8*16 + 16; a++) s += row[a]*g_k[a];
            s += __shfl_xor_sync(0xffffffffu, s, 1);
            s += __shfl_xor_sync(0xffffffffu, s, 2);
            s += __shfl_xor_sync(0xffffffffu, s, 4);
            if (l8 == 0) {
                float val = g_q[i] + s;
                g_v[i] = val;
                vs_all[(size_t)slot*NS + i] = val;
            }
        } else if (b == 44) {
            float* red = sh;
            float s = (t < NC) ? g_k[t]*g_q[NS+t] : 0.f;
            red[t] = s; __syncthreads();
            for (int st = 256; st > 0; st >>= 1) { if (t < st) red[t] += red[t+st]; __syncthreads(); }
            if (t == 0) g_delta[step] = 0.5f*red[0] + 0.5f*g_fVf + g_fv;
        }
        gbar(++phase);
    }

    if (b == 0 && t == 0) {
        float run = 0.f;
        for (int i = 0; i < HOR; i++) {
            run += g_delta[i];
            co_all[HOR-1-i] = run;
        }
    }
}

extern "C" void kernel_launch(void* const* d_in, const int* in_sizes, int n_in,
                              void* d_out, int out_size) {
    const float* F = (const float*)d_in[0];
    const float* f = (const float*)d_in[1];
    const float* C = (const float*)d_in[2];
    const float* c = (const float*)d_in[3];
    float* out = (float*)d_out;

    const int SMEM = 128*129*4;   // 66048 B (chol/trsm footprint; GEMM pipeline uses ~43KB)
    cudaFuncSetAttribute(lqr_persistent, cudaFuncAttributeMaxDynamicSharedMemorySize, SMEM);

    lqr_persistent<<<NB, NT, SMEM>>>(F, f, C, c, out);
}